// round 2
// baseline (speedup 1.0000x reference)
#include <cuda_runtime.h>
#include <cuda_bf16.h>

#define NN 40000      // nodes
#define NE 640000     // edges
#define FD 128        // feature / hidden dim
#define NG 64         // graphs
#define NC 10         // classes
#define GF (NG*FD)

// ---------------- scratch (device globals; no allocations allowed) ----------
__device__ int   g_deg[NN];        // in-degree (without self loop)
__device__ int   g_rowptr[NN + 1];
__device__ int   g_cursor[NN];
__device__ int   g_csr[NE];
__device__ float g_dinv[NN];
__device__ int   g_gcnt[NG];
__device__ float g_y[NN * FD];     // (X @ W) * dinv[row]
__device__ float g_h[NN * FD];     // post-aggregation hidden
__device__ float g_pool[GF];

// ---------------- zero scratch ----------------------------------------------
__global__ void zero_kernel() {
    int i = blockIdx.x * blockDim.x + threadIdx.x;
    if (i < NN) g_deg[i] = 0;
    if (i < GF) g_pool[i] = 0.0f;
    if (i < NG) g_gcnt[i] = 0;
}

// ---------------- degree count ----------------------------------------------
__global__ void deg_kernel(const int* __restrict__ dst) {
    int e = blockIdx.x * blockDim.x + threadIdx.x;
    if (e < NE) atomicAdd(&g_deg[dst[e]], 1);
}

// ---------------- per-node: dinv + graph counts ------------------------------
__global__ void node_kernel(const int* __restrict__ batch) {
    int v = blockIdx.x * blockDim.x + threadIdx.x;
    if (v < NN) {
        g_dinv[v] = rsqrtf((float)(g_deg[v] + 1));   // self-loop => deg >= 1
        atomicAdd(&g_gcnt[batch[v]], 1);
    }
}

// ---------------- exclusive scan over g_deg (single block) -------------------
__global__ void scan_kernel() {
    const int T = 1024, CH = 40;   // 1024*40 = 40960 >= NN
    __shared__ int sums[T];
    int t = threadIdx.x;
    int base = t * CH;
    int s = 0;
    for (int i = 0; i < CH; i++) {
        int idx = base + i;
        if (idx < NN) s += g_deg[idx];
    }
    sums[t] = s;
    __syncthreads();
    // Hillis-Steele inclusive scan
    for (int off = 1; off < T; off <<= 1) {
        int v = (t >= off) ? sums[t - off] : 0;
        __syncthreads();
        sums[t] += v;
        __syncthreads();
    }
    int run = (t == 0) ? 0 : sums[t - 1];
    for (int i = 0; i < CH; i++) {
        int idx = base + i;
        if (idx < NN) {
            g_rowptr[idx] = run;
            g_cursor[idx] = run;
            run += g_deg[idx];
        }
    }
    if (t == T - 1) g_rowptr[NN] = sums[T - 1];
}

// ---------------- CSR fill (dst-sorted edge list) ----------------------------
__global__ void fill_kernel(const int* __restrict__ src, const int* __restrict__ dst) {
    int e = blockIdx.x * blockDim.x + threadIdx.x;
    if (e < NE) {
        int d = dst[e];
        int pos = atomicAdd(&g_cursor[d], 1);
        g_csr[pos] = src[e];
    }
}

// ---------------- GEMM: Y = (A @ W) * dinv[row] ------------------------------
// Block: 256 threads, tile 128 rows x 128 cols, 8x8 micro-tile per thread.
// K chunked by 32; A staged transposed (conflict-free broadcast reads),
// W chunk staged contiguous. Static smem ~33KB -> good occupancy.
__global__ __launch_bounds__(256) void gemm_scale_kernel(
    const float* __restrict__ A, const float* __restrict__ W,
    float* __restrict__ Y, int nrows)
{
    __shared__ float Ws[32][FD];        // [k][c]    16 KB
    __shared__ float As[32][FD + 4];    // [k][row]  16.5 KB (pad keeps 16B align: 132*4=528, 528%16==0)

    int tid  = threadIdx.x;
    int row0 = blockIdx.x * 128;
    int tx = tid & 15, ty = tid >> 4;
    int rBase = ty * 8, cBase = tx * 8;

    float acc[8][8];
#pragma unroll
    for (int r = 0; r < 8; r++)
#pragma unroll
        for (int c = 0; c < 8; c++) acc[r][c] = 0.0f;

    const float4* A4 = (const float4*)A;
    const float4* W4 = (const float4*)W;

    for (int k0 = 0; k0 < FD; k0 += 32) {
        // stage W chunk: rows k0..k0+31, contiguous in W -> 1024 float4
        {
            float4* Wsm4 = (float4*)&Ws[0][0];
            for (int j = tid; j < 1024; j += 256)
                Wsm4[j] = W4[k0 * 32 + j];
        }
        // stage A chunk transposed: As[k][row]
        for (int j = tid; j < 1024; j += 256) {
            int r = j >> 3, kq = j & 7;               // 8 float4 per row (32 k)
            int gr = row0 + r;
            float4 v = (gr < nrows) ? A4[gr * 32 + (k0 >> 2) + kq]
                                    : make_float4(0.f, 0.f, 0.f, 0.f);
            int kk = kq * 4;
            As[kk + 0][r] = v.x;
            As[kk + 1][r] = v.y;
            As[kk + 2][r] = v.z;
            As[kk + 3][r] = v.w;
        }
        __syncthreads();

#pragma unroll 8
        for (int k = 0; k < 32; k++) {
            float4 a0 = *(const float4*)&As[k][rBase];
            float4 a1 = *(const float4*)&As[k][rBase + 4];
            float4 w0 = *(const float4*)&Ws[k][cBase];
            float4 w1 = *(const float4*)&Ws[k][cBase + 4];
            float a[8] = {a0.x, a0.y, a0.z, a0.w, a1.x, a1.y, a1.z, a1.w};
            float w[8] = {w0.x, w0.y, w0.z, w0.w, w1.x, w1.y, w1.z, w1.w};
#pragma unroll
            for (int r = 0; r < 8; r++)
#pragma unroll
                for (int c = 0; c < 8; c++)
                    acc[r][c] = fmaf(a[r], w[c], acc[r][c]);
        }
        __syncthreads();
    }

    // epilogue: scale by dinv[row], store
#pragma unroll
    for (int r = 0; r < 8; r++) {
        int gr = row0 + rBase + r;
        if (gr < nrows) {
            float d = g_dinv[gr];
            float4 o0 = make_float4(acc[r][0] * d, acc[r][1] * d, acc[r][2] * d, acc[r][3] * d);
            float4 o1 = make_float4(acc[r][4] * d, acc[r][5] * d, acc[r][6] * d, acc[r][7] * d);
            *(float4*)&Y[gr * FD + cBase]     = o0;
            *(float4*)&Y[gr * FD + cBase + 4] = o1;
        }
    }
}

// ---------------- aggregation: out[v] = relu(dinv[v]*(y[v]+sum y[src]) + b) --
// warp per node; lane owns 4 features (float4). Optionally fused mean-pool
// accumulation (layer 2).
template <bool POOL>
__global__ __launch_bounds__(256) void agg_kernel(
    const float* __restrict__ y, const float* __restrict__ bias,
    const int* __restrict__ batch, float* __restrict__ out)
{
    int warp = (blockIdx.x * blockDim.x + threadIdx.x) >> 5;
    int lane = threadIdx.x & 31;
    if (warp >= NN) return;

    const float4* y4 = (const float4*)y;
    float4 acc = y4[warp * 32 + lane];        // self-loop term (y already dinv-scaled)

    int i   = g_rowptr[warp];
    int end = g_rowptr[warp + 1];
    for (; i + 4 <= end; i += 4) {
        int s0 = g_csr[i], s1 = g_csr[i + 1], s2 = g_csr[i + 2], s3 = g_csr[i + 3];
        float4 a0 = y4[s0 * 32 + lane];
        float4 a1 = y4[s1 * 32 + lane];
        float4 a2 = y4[s2 * 32 + lane];
        float4 a3 = y4[s3 * 32 + lane];
        acc.x += a0.x + a1.x + a2.x + a3.x;
        acc.y += a0.y + a1.y + a2.y + a3.y;
        acc.z += a0.z + a1.z + a2.z + a3.z;
        acc.w += a0.w + a1.w + a2.w + a3.w;
    }
    for (; i < end; i++) {
        int s = g_csr[i];
        float4 a = y4[s * 32 + lane];
        acc.x += a.x; acc.y += a.y; acc.z += a.z; acc.w += a.w;
    }

    float d = g_dinv[warp];
    float4 bv = ((const float4*)bias)[lane];
    float4 r;
    r.x = fmaxf(fmaf(acc.x, d, bv.x), 0.0f);
    r.y = fmaxf(fmaf(acc.y, d, bv.y), 0.0f);
    r.z = fmaxf(fmaf(acc.z, d, bv.z), 0.0f);
    r.w = fmaxf(fmaf(acc.w, d, bv.w), 0.0f);
    ((float4*)out)[warp * 32 + lane] = r;

    if (POOL) {
        int g = batch[warp];
        float* p = &g_pool[g * FD + lane * 4];
        atomicAdd(p + 0, r.x);
        atomicAdd(p + 1, r.y);
        atomicAdd(p + 2, r.z);
        atomicAdd(p + 3, r.w);
    }
}

// ---------------- head: logits = (pool/cnt) @ lin_w + lin_b ------------------
__global__ void head_kernel(const float* __restrict__ lin_w,
                            const float* __restrict__ lin_b,
                            float* __restrict__ out)
{
    int g = blockIdx.x;     // 64 blocks, 128 threads
    int t = threadIdx.x;
    float invc = 1.0f / fmaxf((float)g_gcnt[g], 1.0f);
    float v = g_pool[g * FD + t] * invc;
    __shared__ float red[FD];
    for (int c = 0; c < NC; c++) {
        red[t] = v * lin_w[t * NC + c];
        __syncthreads();
        for (int off = 64; off > 0; off >>= 1) {
            if (t < off) red[t] += red[t + off];
            __syncthreads();
        }
        if (t == 0) out[g * NC + c] = red[0] + lin_b[c];
        __syncthreads();
    }
}

// ---------------- launch -----------------------------------------------------
extern "C" void kernel_launch(void* const* d_in, const int* in_sizes, int n_in,
                              void* d_out, int out_size)
{
    const float* x     = (const float*)d_in[0];
    const int*   ei    = (const int*)  d_in[1];
    const int*   batch = (const int*)  d_in[2];
    const float* W1    = (const float*)d_in[3];
    const float* b1    = (const float*)d_in[4];
    const float* W2    = (const float*)d_in[5];
    const float* b2    = (const float*)d_in[6];
    const float* lw    = (const float*)d_in[7];
    const float* lb    = (const float*)d_in[8];
    float* out = (float*)d_out;

    const int* src = ei;        // edge_index[0]
    const int* dst = ei + NE;   // edge_index[1]

    float* y = nullptr; float* h = nullptr;
    cudaGetSymbolAddress((void**)&y, g_y);
    cudaGetSymbolAddress((void**)&h, g_h);

    const int nodeBlocks = (NN + 255) / 256;   // 157
    const int edgeBlocks = (NE + 255) / 256;   // 2500
    const int gemmBlocks = (NN + 127) / 128;   // 313
    const int aggBlocks  = (NN * 32 + 255) / 256;  // 5000

    zero_kernel<<<nodeBlocks, 256>>>();
    deg_kernel<<<edgeBlocks, 256>>>(dst);
    node_kernel<<<nodeBlocks, 256>>>(batch);
    scan_kernel<<<1, 1024>>>();
    fill_kernel<<<edgeBlocks, 256>>>(src, dst);

    // layer 1
    gemm_scale_kernel<<<gemmBlocks, 256>>>(x, W1, y, NN);
    agg_kernel<false><<<aggBlocks, 256>>>(y, b1, batch, h);

    // layer 2 (pool fused)
    gemm_scale_kernel<<<gemmBlocks, 256>>>(h, W2, y, NN);
    agg_kernel<true><<<aggBlocks, 256>>>(y, b2, batch, h);

    // head
    head_kernel<<<NG, FD>>>(lw, lb, out);
}

// round 4
// speedup vs baseline: 1.2111x; 1.2111x over previous
#include <cuda_runtime.h>
#include <cuda_bf16.h>

#define NN 40000      // nodes
#define NE 640000     // edges
#define FD 128        // feature / hidden dim
#define NG 64         // graphs
#define NC 10         // classes
#define GF (NG*FD)
#define SCAN_BLKS 40  // 40 * 1024 = 40960 >= NN

// ---------------- scratch (device globals; no allocations allowed) ----------
__device__ int   g_deg[NN];        // in-degree (without self loop)
__device__ int   g_rowptr[NN + 1];
__device__ int   g_cursor[NN];
__device__ int   g_csr[NE];
__device__ float g_dinv[NN];
__device__ int   g_gcnt[NG];
__device__ int   g_bsum[SCAN_BLKS];
__device__ int   g_boff[SCAN_BLKS];
__device__ float g_y[NN * FD];     // (X @ W) * dinv[row]
__device__ float g_h[NN * FD];     // post-aggregation hidden
__device__ float g_pool[GF];

// ---------------- zero scratch ----------------------------------------------
__global__ void zero_kernel() {
    int i = blockIdx.x * blockDim.x + threadIdx.x;
    if (i < NN) g_deg[i] = 0;
    if (i < GF) g_pool[i] = 0.0f;
    if (i < NG) g_gcnt[i] = 0;
}

// ---------------- degree count ----------------------------------------------
__global__ void deg_kernel(const int* __restrict__ dst) {
    int e = blockIdx.x * blockDim.x + threadIdx.x;
    if (e < NE) atomicAdd(&g_deg[dst[e]], 1);
}

// ---------------- per-node: dinv + graph counts ------------------------------
__global__ void node_kernel(const int* __restrict__ batch) {
    int v = blockIdx.x * blockDim.x + threadIdx.x;
    if (v < NN) {
        g_dinv[v] = rsqrtf((float)(g_deg[v] + 1));   // self-loop => deg >= 1
        atomicAdd(&g_gcnt[batch[v]], 1);
    }
}

// ---------------- scan phase A: per-block exclusive scan + block sums --------
__global__ __launch_bounds__(1024) void scanA_kernel() {
    __shared__ int wsum[32];
    int b = blockIdx.x, t = threadIdx.x;
    int i = b * 1024 + t;
    int v = (i < NN) ? g_deg[i] : 0;
    int lane = t & 31, w = t >> 5;
    // warp inclusive scan
    int x = v;
#pragma unroll
    for (int o = 1; o < 32; o <<= 1) {
        int y = __shfl_up_sync(0xffffffffu, x, o);
        if (lane >= o) x += y;
    }
    if (lane == 31) wsum[w] = x;
    __syncthreads();
    if (w == 0) {
        int s = wsum[lane];
#pragma unroll
        for (int o = 1; o < 32; o <<= 1) {
            int y = __shfl_up_sync(0xffffffffu, s, o);
            if (lane >= o) s += y;
        }
        wsum[lane] = s;
    }
    __syncthreads();
    int incl = x + ((w > 0) ? wsum[w - 1] : 0);
    if (i < NN) g_rowptr[i] = incl - v;       // block-local exclusive
    if (t == 1023) g_bsum[b] = incl;          // block total
}

// ---------------- scan phase B: scan the 40 block sums (1 warp-ish) ----------
__global__ void scanB_kernel() {
    __shared__ int s[64];
    int t = threadIdx.x;                       // 64 threads
    s[t] = (t < SCAN_BLKS) ? g_bsum[t] : 0;
    __syncthreads();
    for (int o = 1; o < 64; o <<= 1) {
        int v = (t >= o) ? s[t - o] : 0;
        __syncthreads();
        s[t] += v;
        __syncthreads();
    }
    if (t < SCAN_BLKS) g_boff[t] = (t > 0) ? s[t - 1] : 0;  // exclusive
}

// ---------------- scan phase C: apply block offsets, init cursor -------------
__global__ __launch_bounds__(1024) void scanC_kernel() {
    int b = blockIdx.x, t = threadIdx.x;
    int i = b * 1024 + t;
    if (i < NN) {
        int r = g_rowptr[i] + g_boff[b];
        g_rowptr[i] = r;
        g_cursor[i] = r;
    }
    if (b == 0 && t == 0) g_rowptr[NN] = NE;
}

// ---------------- CSR fill (dst-sorted edge list) ----------------------------
__global__ void fill_kernel(const int* __restrict__ src, const int* __restrict__ dst) {
    int e = blockIdx.x * blockDim.x + threadIdx.x;
    if (e < NE) {
        int d = dst[e];
        int pos = atomicAdd(&g_cursor[d], 1);
        g_csr[pos] = src[e];
    }
}

// ---------------- GEMM: Y = (A @ W) * dinv[row] ------------------------------
// Block: 256 threads, tile 128 rows x 128 cols, 8x8 micro-tile per thread.
__global__ __launch_bounds__(256) void gemm_scale_kernel(
    const float* __restrict__ A, const float* __restrict__ W,
    float* __restrict__ Y, int nrows)
{
    __shared__ float Ws[32][FD];        // [k][c]    16 KB
    __shared__ float As[32][FD + 4];    // [k][row]  16.5 KB

    int tid  = threadIdx.x;
    int row0 = blockIdx.x * 128;
    int tx = tid & 15, ty = tid >> 4;
    int rBase = ty * 8, cBase = tx * 8;

    float acc[8][8];
#pragma unroll
    for (int r = 0; r < 8; r++)
#pragma unroll
        for (int c = 0; c < 8; c++) acc[r][c] = 0.0f;

    const float4* A4 = (const float4*)A;
    const float4* W4 = (const float4*)W;

    for (int k0 = 0; k0 < FD; k0 += 32) {
        {
            float4* Wsm4 = (float4*)&Ws[0][0];
            for (int j = tid; j < 1024; j += 256)
                Wsm4[j] = W4[k0 * 32 + j];
        }
        for (int j = tid; j < 1024; j += 256) {
            int r = j >> 3, kq = j & 7;
            int gr = row0 + r;
            float4 v = (gr < nrows) ? A4[gr * 32 + (k0 >> 2) + kq]
                                    : make_float4(0.f, 0.f, 0.f, 0.f);
            int kk = kq * 4;
            As[kk + 0][r] = v.x;
            As[kk + 1][r] = v.y;
            As[kk + 2][r] = v.z;
            As[kk + 3][r] = v.w;
        }
        __syncthreads();

#pragma unroll 8
        for (int k = 0; k < 32; k++) {
            float4 a0 = *(const float4*)&As[k][rBase];
            float4 a1 = *(const float4*)&As[k][rBase + 4];
            float4 w0 = *(const float4*)&Ws[k][cBase];
            float4 w1 = *(const float4*)&Ws[k][cBase + 4];
            float a[8] = {a0.x, a0.y, a0.z, a0.w, a1.x, a1.y, a1.z, a1.w};
            float w[8] = {w0.x, w0.y, w0.z, w0.w, w1.x, w1.y, w1.z, w1.w};
#pragma unroll
            for (int r = 0; r < 8; r++)
#pragma unroll
                for (int c = 0; c < 8; c++)
                    acc[r][c] = fmaf(a[r], w[c], acc[r][c]);
        }
        __syncthreads();
    }

#pragma unroll
    for (int r = 0; r < 8; r++) {
        int gr = row0 + rBase + r;
        if (gr < nrows) {
            float d = g_dinv[gr];
            float4 o0 = make_float4(acc[r][0] * d, acc[r][1] * d, acc[r][2] * d, acc[r][3] * d);
            float4 o1 = make_float4(acc[r][4] * d, acc[r][5] * d, acc[r][6] * d, acc[r][7] * d);
            *(float4*)&Y[gr * FD + cBase]     = o0;
            *(float4*)&Y[gr * FD + cBase + 4] = o1;
        }
    }
}

// ---------------- aggregation: out[v] = relu(dinv[v]*(y[v]+sum y[src]) + b) --
template <bool POOL>
__global__ __launch_bounds__(256) void agg_kernel(
    const float* __restrict__ y, const float* __restrict__ bias,
    const int* __restrict__ batch, float* __restrict__ out)
{
    int warp = (blockIdx.x * blockDim.x + threadIdx.x) >> 5;
    int lane = threadIdx.x & 31;
    if (warp >= NN) return;

    const float4* y4 = (const float4*)y;
    float4 acc = y4[warp * 32 + lane];        // self-loop term (y already dinv-scaled)

    int i   = g_rowptr[warp];
    int end = g_rowptr[warp + 1];
    for (; i + 4 <= end; i += 4) {
        int s0 = g_csr[i], s1 = g_csr[i + 1], s2 = g_csr[i + 2], s3 = g_csr[i + 3];
        float4 a0 = y4[s0 * 32 + lane];
        float4 a1 = y4[s1 * 32 + lane];
        float4 a2 = y4[s2 * 32 + lane];
        float4 a3 = y4[s3 * 32 + lane];
        acc.x += a0.x + a1.x + a2.x + a3.x;
        acc.y += a0.y + a1.y + a2.y + a3.y;
        acc.z += a0.z + a1.z + a2.z + a3.z;
        acc.w += a0.w + a1.w + a2.w + a3.w;
    }
    for (; i < end; i++) {
        int s = g_csr[i];
        float4 a = y4[s * 32 + lane];
        acc.x += a.x; acc.y += a.y; acc.z += a.z; acc.w += a.w;
    }

    float d = g_dinv[warp];
    float4 bv = ((const float4*)bias)[lane];
    float4 r;
    r.x = fmaxf(fmaf(acc.x, d, bv.x), 0.0f);
    r.y = fmaxf(fmaf(acc.y, d, bv.y), 0.0f);
    r.z = fmaxf(fmaf(acc.z, d, bv.z), 0.0f);
    r.w = fmaxf(fmaf(acc.w, d, bv.w), 0.0f);
    ((float4*)out)[warp * 32 + lane] = r;

    if (POOL) {
        int g = batch[warp];
        float* p = &g_pool[g * FD + lane * 4];
        atomicAdd(p + 0, r.x);
        atomicAdd(p + 1, r.y);
        atomicAdd(p + 2, r.z);
        atomicAdd(p + 3, r.w);
    }
}

// ---------------- head: logits = (pool/cnt) @ lin_w + lin_b ------------------
__global__ void head_kernel(const float* __restrict__ lin_w,
                            const float* __restrict__ lin_b,
                            float* __restrict__ out)
{
    int g = blockIdx.x;     // 64 blocks, 128 threads
    int t = threadIdx.x;
    float invc = 1.0f / fmaxf((float)g_gcnt[g], 1.0f);
    float v = g_pool[g * FD + t] * invc;
    __shared__ float red[FD];
    for (int c = 0; c < NC; c++) {
        red[t] = v * lin_w[t * NC + c];
        __syncthreads();
        for (int off = 64; off > 0; off >>= 1) {
            if (t < off) red[t] += red[t + off];
            __syncthreads();
        }
        if (t == 0) out[g * NC + c] = red[0] + lin_b[c];
        __syncthreads();
    }
}

// ---------------- launch -----------------------------------------------------
extern "C" void kernel_launch(void* const* d_in, const int* in_sizes, int n_in,
                              void* d_out, int out_size)
{
    const float* x     = (const float*)d_in[0];
    const int*   ei    = (const int*)  d_in[1];
    const int*   batch = (const int*)  d_in[2];
    const float* W1    = (const float*)d_in[3];
    const float* b1    = (const float*)d_in[4];
    const float* W2    = (const float*)d_in[5];
    const float* b2    = (const float*)d_in[6];
    const float* lw    = (const float*)d_in[7];
    const float* lb    = (const float*)d_in[8];
    float* out = (float*)d_out;

    const int* src = ei;        // edge_index[0]
    const int* dst = ei + NE;   // edge_index[1]

    float* y = nullptr; float* h = nullptr;
    cudaGetSymbolAddress((void**)&y, g_y);
    cudaGetSymbolAddress((void**)&h, g_h);

    const int nodeBlocks = (NN + 255) / 256;       // 157
    const int edgeBlocks = (NE + 255) / 256;       // 2500
    const int gemmBlocks = (NN + 127) / 128;       // 313
    const int aggBlocks  = (NN * 32 + 255) / 256;  // 5000

    // prep chain (launch order also positions gemm1 as the 6th launch so the
    // ncu capture (-s 5 -c 1) profiles the GEMM next round)
    zero_kernel<<<nodeBlocks, 256>>>();            // 1
    deg_kernel<<<edgeBlocks, 256>>>(dst);          // 2
    node_kernel<<<nodeBlocks, 256>>>(batch);       // 3
    scanA_kernel<<<SCAN_BLKS, 1024>>>();           // 4
    scanB_kernel<<<1, 64>>>();                     // 5

    // layer 1 GEMM (depends only on dinv from node_kernel)
    gemm_scale_kernel<<<gemmBlocks, 256>>>(x, W1, y, NN);   // 6  <-- profiled

    scanC_kernel<<<SCAN_BLKS, 1024>>>();           // 7
    fill_kernel<<<edgeBlocks, 256>>>(src, dst);    // 8

    // layer 1 aggregation
    agg_kernel<false><<<aggBlocks, 256>>>(y, b1, batch, h);

    // layer 2 (pool fused)
    gemm_scale_kernel<<<gemmBlocks, 256>>>(h, W2, y, NN);
    agg_kernel<true><<<aggBlocks, 256>>>(y, b2, batch, h);

    // head
    head_kernel<<<NG, FD>>>(lw, lb, out);
}

// round 5
// speedup vs baseline: 1.3067x; 1.0789x over previous
#include <cuda_runtime.h>
#include <cuda_bf16.h>

#define NN 40000      // nodes
#define NE 640000     // edges
#define FD 128        // feature / hidden dim
#define NG 64         // graphs
#define NC 10         // classes
#define GF (NG*FD)
#define SCAN_BLKS 40  // 40 * 1024 = 40960 >= NN

// ---------------- scratch (device globals; no allocations allowed) ----------
__device__ int   g_deg[NN];        // in-degree (without self loop)
__device__ int   g_rowptr[NN + 1];
__device__ int   g_cursor[NN];
__device__ int   g_csr[NE];
__device__ float g_dinv[NN];
__device__ int   g_gcnt[NG];
__device__ int   g_bsum[SCAN_BLKS];
__device__ int   g_boff[SCAN_BLKS];
__device__ float g_y[NN * FD];     // (X @ W) * dinv[row]
__device__ float g_h[NN * FD];     // post-aggregation hidden
__device__ float g_pool[GF];

// ---------------- zero scratch ----------------------------------------------
__global__ void zero_kernel() {
    int i = blockIdx.x * blockDim.x + threadIdx.x;
    if (i < NN) g_deg[i] = 0;
    if (i < GF) g_pool[i] = 0.0f;
    if (i < NG) g_gcnt[i] = 0;
}

// ---------------- degree count ----------------------------------------------
__global__ void deg_kernel(const int* __restrict__ dst) {
    int e = blockIdx.x * blockDim.x + threadIdx.x;
    if (e < NE) atomicAdd(&g_deg[dst[e]], 1);
}

// ---------------- per-node: dinv + graph counts ------------------------------
__global__ void node_kernel(const int* __restrict__ batch) {
    int v = blockIdx.x * blockDim.x + threadIdx.x;
    if (v < NN) {
        g_dinv[v] = rsqrtf((float)(g_deg[v] + 1));   // self-loop => deg >= 1
        atomicAdd(&g_gcnt[batch[v]], 1);
    }
}

// ---------------- scan phase A: per-block exclusive scan + block sums --------
__global__ __launch_bounds__(1024) void scanA_kernel() {
    __shared__ int wsum[32];
    int b = blockIdx.x, t = threadIdx.x;
    int i = b * 1024 + t;
    int v = (i < NN) ? g_deg[i] : 0;
    int lane = t & 31, w = t >> 5;
    int x = v;
#pragma unroll
    for (int o = 1; o < 32; o <<= 1) {
        int y = __shfl_up_sync(0xffffffffu, x, o);
        if (lane >= o) x += y;
    }
    if (lane == 31) wsum[w] = x;
    __syncthreads();
    if (w == 0) {
        int s = wsum[lane];
#pragma unroll
        for (int o = 1; o < 32; o <<= 1) {
            int y = __shfl_up_sync(0xffffffffu, s, o);
            if (lane >= o) s += y;
        }
        wsum[lane] = s;
    }
    __syncthreads();
    int incl = x + ((w > 0) ? wsum[w - 1] : 0);
    if (i < NN) g_rowptr[i] = incl - v;       // block-local exclusive
    if (t == 1023) g_bsum[b] = incl;          // block total
}

// ---------------- scan phase B: scan the 40 block sums -----------------------
__global__ void scanB_kernel() {
    __shared__ int s[64];
    int t = threadIdx.x;                       // 64 threads
    s[t] = (t < SCAN_BLKS) ? g_bsum[t] : 0;
    __syncthreads();
    for (int o = 1; o < 64; o <<= 1) {
        int v = (t >= o) ? s[t - o] : 0;
        __syncthreads();
        s[t] += v;
        __syncthreads();
    }
    if (t < SCAN_BLKS) g_boff[t] = (t > 0) ? s[t - 1] : 0;  // exclusive
}

// ---------------- scan phase C: apply block offsets, init cursor -------------
__global__ __launch_bounds__(1024) void scanC_kernel() {
    int b = blockIdx.x, t = threadIdx.x;
    int i = b * 1024 + t;
    if (i < NN) {
        int r = g_rowptr[i] + g_boff[b];
        g_rowptr[i] = r;
        g_cursor[i] = r;
    }
    if (b == 0 && t == 0) g_rowptr[NN] = NE;
}

// ---------------- CSR fill (dst-sorted edge list) ----------------------------
__global__ void fill_kernel(const int* __restrict__ src, const int* __restrict__ dst) {
    int e = blockIdx.x * blockDim.x + threadIdx.x;
    if (e < NE) {
        int d = dst[e];
        int pos = atomicAdd(&g_cursor[d], 1);
        g_csr[pos] = src[e];
    }
}

// ---------------- GEMM: Y = (A @ W) * dinv[row] ------------------------------
// 256 threads, tile 128x128, 8x8 micro-tile. Double-buffered smem (2 stages),
// one barrier per K-chunk; next chunk's global loads issued before compute.
// Dynamic smem: 2 * (Ws 32x128 + As 32x132) floats = 66560 B.
#define WS_OFF(s)  ((s) * 4096)
#define AS_OFF(s)  (8192 + (s) * 4224)

__global__ __launch_bounds__(256) void gemm_scale_kernel(
    const float* __restrict__ A, const float* __restrict__ W,
    float* __restrict__ Y, int nrows)
{
    extern __shared__ float sm[];

    int tid  = threadIdx.x;
    int row0 = blockIdx.x * 128;
    int tx = tid & 15, ty = tid >> 4;
    int rBase = ty * 8, cBase = tx * 8;

    float acc[8][8];
#pragma unroll
    for (int r = 0; r < 8; r++)
#pragma unroll
        for (int c = 0; c < 8; c++) acc[r][c] = 0.0f;

    const float4* A4 = (const float4*)A;
    const float4* W4 = (const float4*)W;

    // stage loader: chunk k0 -> stage s
    auto load_stage = [&](int s, int k0) {
        float4* Wsm4 = (float4*)&sm[WS_OFF(s)];
#pragma unroll
        for (int j = tid; j < 1024; j += 256)
            Wsm4[j] = W4[k0 * 32 + j];
#pragma unroll
        for (int j = tid; j < 1024; j += 256) {
            int r = j >> 3, kq = j & 7;
            int gr = row0 + r;
            float4 v = (gr < nrows) ? A4[gr * 32 + (k0 >> 2) + kq]
                                    : make_float4(0.f, 0.f, 0.f, 0.f);
            int kk = kq * 4;
            float* As = &sm[AS_OFF(s)];
            As[(kk + 0) * 132 + r] = v.x;
            As[(kk + 1) * 132 + r] = v.y;
            As[(kk + 2) * 132 + r] = v.z;
            As[(kk + 3) * 132 + r] = v.w;
        }
    };

    load_stage(0, 0);
    __syncthreads();

#pragma unroll
    for (int chunk = 0; chunk < 4; chunk++) {
        int s = chunk & 1;
        if (chunk < 3) load_stage(s ^ 1, (chunk + 1) * 32);

        const float* Ws = &sm[WS_OFF(s)];
        const float* As = &sm[AS_OFF(s)];
#pragma unroll 8
        for (int k = 0; k < 32; k++) {
            float4 a0 = *(const float4*)&As[k * 132 + rBase];
            float4 a1 = *(const float4*)&As[k * 132 + rBase + 4];
            float4 w0 = *(const float4*)&Ws[k * 128 + cBase];
            float4 w1 = *(const float4*)&Ws[k * 128 + cBase + 4];
            float a[8] = {a0.x, a0.y, a0.z, a0.w, a1.x, a1.y, a1.z, a1.w};
            float w[8] = {w0.x, w0.y, w0.z, w0.w, w1.x, w1.y, w1.z, w1.w};
#pragma unroll
            for (int r = 0; r < 8; r++)
#pragma unroll
                for (int c = 0; c < 8; c++)
                    acc[r][c] = fmaf(a[r], w[c], acc[r][c]);
        }
        __syncthreads();
    }

#pragma unroll
    for (int r = 0; r < 8; r++) {
        int gr = row0 + rBase + r;
        if (gr < nrows) {
            float d = g_dinv[gr];
            float4 o0 = make_float4(acc[r][0] * d, acc[r][1] * d, acc[r][2] * d, acc[r][3] * d);
            float4 o1 = make_float4(acc[r][4] * d, acc[r][5] * d, acc[r][6] * d, acc[r][7] * d);
            *(float4*)&Y[gr * FD + cBase]     = o0;
            *(float4*)&Y[gr * FD + cBase + 4] = o1;
        }
    }
}
#define GEMM_SMEM 66560

// ---------------- aggregation: out[v] = relu(dinv[v]*(y[v]+sum y[src]) + b) --
template <bool POOL>
__global__ __launch_bounds__(256) void agg_kernel(
    const float* __restrict__ y, const float* __restrict__ bias,
    const int* __restrict__ batch, float* __restrict__ out)
{
    int warp = (blockIdx.x * blockDim.x + threadIdx.x) >> 5;
    int lane = threadIdx.x & 31;
    if (warp >= NN) return;

    const float4* y4 = (const float4*)y;
    float4 acc = y4[warp * 32 + lane];        // self-loop term (y already dinv-scaled)

    int i   = g_rowptr[warp];
    int end = g_rowptr[warp + 1];

    // 8-wide: 8 independent gathers in flight per lane
    for (; i + 8 <= end; i += 8) {
        int s0 = g_csr[i],     s1 = g_csr[i + 1], s2 = g_csr[i + 2], s3 = g_csr[i + 3];
        int s4 = g_csr[i + 4], s5 = g_csr[i + 5], s6 = g_csr[i + 6], s7 = g_csr[i + 7];
        float4 a0 = y4[s0 * 32 + lane];
        float4 a1 = y4[s1 * 32 + lane];
        float4 a2 = y4[s2 * 32 + lane];
        float4 a3 = y4[s3 * 32 + lane];
        float4 a4 = y4[s4 * 32 + lane];
        float4 a5 = y4[s5 * 32 + lane];
        float4 a6 = y4[s6 * 32 + lane];
        float4 a7 = y4[s7 * 32 + lane];
        acc.x += ((a0.x + a1.x) + (a2.x + a3.x)) + ((a4.x + a5.x) + (a6.x + a7.x));
        acc.y += ((a0.y + a1.y) + (a2.y + a3.y)) + ((a4.y + a5.y) + (a6.y + a7.y));
        acc.z += ((a0.z + a1.z) + (a2.z + a3.z)) + ((a4.z + a5.z) + (a6.z + a7.z));
        acc.w += ((a0.w + a1.w) + (a2.w + a3.w)) + ((a4.w + a5.w) + (a6.w + a7.w));
    }
    for (; i + 4 <= end; i += 4) {
        int s0 = g_csr[i], s1 = g_csr[i + 1], s2 = g_csr[i + 2], s3 = g_csr[i + 3];
        float4 a0 = y4[s0 * 32 + lane];
        float4 a1 = y4[s1 * 32 + lane];
        float4 a2 = y4[s2 * 32 + lane];
        float4 a3 = y4[s3 * 32 + lane];
        acc.x += (a0.x + a1.x) + (a2.x + a3.x);
        acc.y += (a0.y + a1.y) + (a2.y + a3.y);
        acc.z += (a0.z + a1.z) + (a2.z + a3.z);
        acc.w += (a0.w + a1.w) + (a2.w + a3.w);
    }
    for (; i < end; i++) {
        int s = g_csr[i];
        float4 a = y4[s * 32 + lane];
        acc.x += a.x; acc.y += a.y; acc.z += a.z; acc.w += a.w;
    }

    float d = g_dinv[warp];
    float4 bv = ((const float4*)bias)[lane];
    float4 r;
    r.x = fmaxf(fmaf(acc.x, d, bv.x), 0.0f);
    r.y = fmaxf(fmaf(acc.y, d, bv.y), 0.0f);
    r.z = fmaxf(fmaf(acc.z, d, bv.z), 0.0f);
    r.w = fmaxf(fmaf(acc.w, d, bv.w), 0.0f);
    ((float4*)out)[warp * 32 + lane] = r;

    if (POOL) {
        int g = batch[warp];
        float* p = &g_pool[g * FD + lane * 4];
        atomicAdd(p + 0, r.x);
        atomicAdd(p + 1, r.y);
        atomicAdd(p + 2, r.z);
        atomicAdd(p + 3, r.w);
    }
}

// ---------------- head: logits = (pool/cnt) @ lin_w + lin_b ------------------
__global__ void head_kernel(const float* __restrict__ lin_w,
                            const float* __restrict__ lin_b,
                            float* __restrict__ out)
{
    int g = blockIdx.x;     // 64 blocks, 128 threads
    int t = threadIdx.x;
    float invc = 1.0f / fmaxf((float)g_gcnt[g], 1.0f);
    float v = g_pool[g * FD + t] * invc;
    __shared__ float red[FD];
    for (int c = 0; c < NC; c++) {
        red[t] = v * lin_w[t * NC + c];
        __syncthreads();
        for (int off = 64; off > 0; off >>= 1) {
            if (t < off) red[t] += red[t + off];
            __syncthreads();
        }
        if (t == 0) out[g * NC + c] = red[0] + lin_b[c];
        __syncthreads();
    }
}

// ---------------- launch -----------------------------------------------------
extern "C" void kernel_launch(void* const* d_in, const int* in_sizes, int n_in,
                              void* d_out, int out_size)
{
    const float* x     = (const float*)d_in[0];
    const int*   ei    = (const int*)  d_in[1];
    const int*   batch = (const int*)  d_in[2];
    const float* W1    = (const float*)d_in[3];
    const float* b1    = (const float*)d_in[4];
    const float* W2    = (const float*)d_in[5];
    const float* b2    = (const float*)d_in[6];
    const float* lw    = (const float*)d_in[7];
    const float* lb    = (const float*)d_in[8];
    float* out = (float*)d_out;

    const int* src = ei;        // edge_index[0]
    const int* dst = ei + NE;   // edge_index[1]

    float* y = nullptr; float* h = nullptr;
    cudaGetSymbolAddress((void**)&y, g_y);
    cudaGetSymbolAddress((void**)&h, g_h);

    cudaFuncSetAttribute(gemm_scale_kernel,
                         cudaFuncAttributeMaxDynamicSharedMemorySize, GEMM_SMEM);

    const int nodeBlocks = (NN + 255) / 256;       // 157
    const int edgeBlocks = (NE + 255) / 256;       // 2500
    const int gemmBlocks = (NN + 127) / 128;       // 313
    const int aggBlocks  = (NN * 32 + 255) / 256;  // 5000

    // ncu (-s 5 -c 1) lands on MY 4th launch (harness prepends 2) -> gemm1.
    zero_kernel<<<nodeBlocks, 256>>>();                           // 1
    deg_kernel<<<edgeBlocks, 256>>>(dst);                         // 2
    node_kernel<<<nodeBlocks, 256>>>(batch);                      // 3
    gemm_scale_kernel<<<gemmBlocks, 256, GEMM_SMEM>>>(x, W1, y, NN); // 4 <-- profiled

    scanA_kernel<<<SCAN_BLKS, 1024>>>();                          // 5
    scanB_kernel<<<1, 64>>>();                                    // 6
    scanC_kernel<<<SCAN_BLKS, 1024>>>();                          // 7
    fill_kernel<<<edgeBlocks, 256>>>(src, dst);                   // 8

    // layer 1 aggregation
    agg_kernel<false><<<aggBlocks, 256>>>(y, b1, batch, h);

    // layer 2 (pool fused)
    gemm_scale_kernel<<<gemmBlocks, 256, GEMM_SMEM>>>(h, W2, y, NN);
    agg_kernel<true><<<aggBlocks, 256>>>(y, b2, batch, h);

    // head
    head_kernel<<<NG, FD>>>(lw, lb, out);
}

// round 6
// speedup vs baseline: 1.3271x; 1.0156x over previous
#include <cuda_runtime.h>
#include <cuda_bf16.h>

#define NN 40000      // nodes
#define NE 640000     // edges
#define FD 128        // feature / hidden dim
#define NG 64         // graphs
#define NC 10         // classes
#define GF (NG*FD)
#define SCAN_BLKS 40  // 40 * 1024 = 40960 >= NN
#define NB 128        // persistent prep blocks (<= 148 SMs -> co-resident)

// ---------------- scratch (device globals; no allocations allowed) ----------
__device__ int   g_deg[NN];
__device__ int   g_rowptr[NN + 1];
__device__ int   g_cursor[NN];
__device__ int   g_csr[NE];
__device__ float g_dinv[NN];
__device__ int   g_gcnt[NG];
__device__ int   g_bsum[SCAN_BLKS];
__device__ float g_y[NN * FD];
__device__ float g_h[NN * FD];
__device__ float g_pool[GF];
__device__ unsigned g_barrier;     // software grid barrier (reset by head_kernel)

// ---------------- fused prep: zero + deg + node + scan (persistent) ---------
__device__ __forceinline__ void gsync(unsigned target) {
    __syncthreads();
    __threadfence();
    if (threadIdx.x == 0) {
        atomicAdd(&g_barrier, 1u);
        while (atomicAdd(&g_barrier, 0u) < target) { }
    }
    __syncthreads();
    __threadfence();
}

__global__ __launch_bounds__(1024) void prep_kernel(
    const int* __restrict__ src, const int* __restrict__ dst,
    const int* __restrict__ batch)
{
    int b = blockIdx.x, t = threadIdx.x;
    int gt = b * 1024 + t;                 // 0 .. 131071
    const int GSTRIDE = NB * 1024;

    // phase 0: zero scratch
    for (int i = gt; i < NN; i += GSTRIDE) g_deg[i] = 0;
    if (gt < GF) g_pool[gt] = 0.0f;
    if (gt < NG) g_gcnt[gt] = 0;
    gsync(NB);

    // phase 1: in-degree count
    for (int e = gt; e < NE; e += GSTRIDE) atomicAdd(&g_deg[dst[e]], 1);
    gsync(2u * NB);

    // phase 2: dinv + graph counts + block-local exclusive scan (blocks 0..39)
    if (gt < NN) {
        g_dinv[gt] = rsqrtf((float)(g_deg[gt] + 1));
        atomicAdd(&g_gcnt[batch[gt]], 1);
    }
    __shared__ int wsum[32];
    int localExcl = 0;
    if (b < SCAN_BLKS) {
        int v = (gt < NN) ? g_deg[gt] : 0;
        int lane = t & 31, w = t >> 5;
        int x = v;
#pragma unroll
        for (int o = 1; o < 32; o <<= 1) {
            int y = __shfl_up_sync(0xffffffffu, x, o);
            if (lane >= o) x += y;
        }
        if (lane == 31) wsum[w] = x;
        __syncthreads();
        if (w == 0) {
            int s = wsum[lane];
#pragma unroll
            for (int o = 1; o < 32; o <<= 1) {
                int y = __shfl_up_sync(0xffffffffu, s, o);
                if (lane >= o) s += y;
            }
            wsum[lane] = s;
        }
        __syncthreads();
        int incl = x + ((w > 0) ? wsum[w - 1] : 0);
        localExcl = incl - v;
        if (t == 1023) g_bsum[b] = incl;
    }
    gsync(3u * NB);

    // phase 3: apply block offsets + cursor init
    if (b < SCAN_BLKS) {
        __shared__ int soff;
        if (t == 0) {
            int s = 0;
            for (int j = 0; j < b; j++) s += g_bsum[j];
            soff = s;
        }
        __syncthreads();
        if (gt < NN) {
            int r = localExcl + soff;
            g_rowptr[gt] = r;
            g_cursor[gt] = r;
        }
    }
    if (gt == 0) g_rowptr[NN] = NE;
}

// ---------------- CSR fill ---------------------------------------------------
__global__ void fill_kernel(const int* __restrict__ src, const int* __restrict__ dst) {
    int e = blockIdx.x * blockDim.x + threadIdx.x;
    if (e < NE) {
        int d = dst[e];
        int pos = atomicAdd(&g_cursor[d], 1);
        g_csr[pos] = src[e];
    }
}

// ---------------- GEMM: Y = (A @ W) * dinv[row] ------------------------------
// 256 threads, tile 128x128, 8x8 micro-tile split 4+4 (conflict-free LDS):
// cols {tx*4..+3, 64+tx*4..+3}, rows {ty*4..+3, 64+ty*4..+3}.
// Double-buffered dynamic smem, one barrier per K-chunk.
#define WS_OFF(s)  ((s) * 4096)
#define AS_OFF(s)  (8192 + (s) * 4224)

__global__ __launch_bounds__(256) void gemm_scale_kernel(
    const float* __restrict__ A, const float* __restrict__ W,
    float* __restrict__ Y, int nrows)
{
    extern __shared__ float sm[];

    int tid  = threadIdx.x;
    int row0 = blockIdx.x * 128;
    int tx = tid & 15, ty = tid >> 4;

    float acc[8][8];
#pragma unroll
    for (int r = 0; r < 8; r++)
#pragma unroll
        for (int c = 0; c < 8; c++) acc[r][c] = 0.0f;

    const float4* A4 = (const float4*)A;
    const float4* W4 = (const float4*)W;

    auto load_stage = [&](int s, int k0) {
        float4* Wsm4 = (float4*)&sm[WS_OFF(s)];
#pragma unroll
        for (int j = tid; j < 1024; j += 256)
            Wsm4[j] = W4[k0 * 32 + j];
#pragma unroll
        for (int j = tid; j < 1024; j += 256) {
            int r = j >> 3, kq = j & 7;
            int gr = row0 + r;
            float4 v = (gr < nrows) ? A4[gr * 32 + (k0 >> 2) + kq]
                                    : make_float4(0.f, 0.f, 0.f, 0.f);
            int kk = kq * 4;
            float* As = &sm[AS_OFF(s)];
            As[(kk + 0) * 132 + r] = v.x;
            As[(kk + 1) * 132 + r] = v.y;
            As[(kk + 2) * 132 + r] = v.z;
            As[(kk + 3) * 132 + r] = v.w;
        }
    };

    load_stage(0, 0);
    __syncthreads();

#pragma unroll
    for (int chunk = 0; chunk < 4; chunk++) {
        int s = chunk & 1;
        if (chunk < 3) load_stage(s ^ 1, (chunk + 1) * 32);

        const float* Ws = &sm[WS_OFF(s)];
        const float* As = &sm[AS_OFF(s)];
#pragma unroll 8
        for (int k = 0; k < 32; k++) {
            float4 a0 = *(const float4*)&As[k * 132 + ty * 4];
            float4 a1 = *(const float4*)&As[k * 132 + 64 + ty * 4];
            float4 w0 = *(const float4*)&Ws[k * 128 + tx * 4];
            float4 w1 = *(const float4*)&Ws[k * 128 + 64 + tx * 4];
            float a[8] = {a0.x, a0.y, a0.z, a0.w, a1.x, a1.y, a1.z, a1.w};
            float w[8] = {w0.x, w0.y, w0.z, w0.w, w1.x, w1.y, w1.z, w1.w};
#pragma unroll
            for (int r = 0; r < 8; r++)
#pragma unroll
                for (int c = 0; c < 8; c++)
                    acc[r][c] = fmaf(a[r], w[c], acc[r][c]);
        }
        __syncthreads();
    }

#pragma unroll
    for (int rr = 0; rr < 8; rr++) {
        int lr = (rr < 4) ? (ty * 4 + rr) : (64 + ty * 4 + rr - 4);
        int gr = row0 + lr;
        if (gr < nrows) {
            float d = g_dinv[gr];
            float4 o0 = make_float4(acc[rr][0] * d, acc[rr][1] * d, acc[rr][2] * d, acc[rr][3] * d);
            float4 o1 = make_float4(acc[rr][4] * d, acc[rr][5] * d, acc[rr][6] * d, acc[rr][7] * d);
            *(float4*)&Y[gr * FD + tx * 4]      = o0;
            *(float4*)&Y[gr * FD + 64 + tx * 4] = o1;
        }
    }
}
#define GEMM_SMEM 66560

// ---------------- aggregation: out[v] = relu(dinv[v]*(y[v]+sum y[src]) + b) --
template <bool POOL>
__global__ __launch_bounds__(256) void agg_kernel(
    const float* __restrict__ y, const float* __restrict__ bias,
    const int* __restrict__ batch, float* __restrict__ out)
{
    int warp = (blockIdx.x * blockDim.x + threadIdx.x) >> 5;
    int lane = threadIdx.x & 31;
    if (warp >= NN) return;

    const float4* y4 = (const float4*)y;
    float4 acc = y4[warp * 32 + lane];        // self-loop term (y already dinv-scaled)

    int i   = g_rowptr[warp];
    int end = g_rowptr[warp + 1];

    // 16-wide: 16 independent gathers in flight per lane (mean degree ~16)
    for (; i + 16 <= end; i += 16) {
        int idx[16];
#pragma unroll
        for (int j = 0; j < 16; j++) idx[j] = g_csr[i + j];
        float4 v[16];
#pragma unroll
        for (int j = 0; j < 16; j++) v[j] = y4[idx[j] * 32 + lane];
        float sx = 0.f, sy = 0.f, sz = 0.f, sw = 0.f;
#pragma unroll
        for (int j = 0; j < 16; j++) { sx += v[j].x; sy += v[j].y; sz += v[j].z; sw += v[j].w; }
        acc.x += sx; acc.y += sy; acc.z += sz; acc.w += sw;
    }
    for (; i + 4 <= end; i += 4) {
        int s0 = g_csr[i], s1 = g_csr[i + 1], s2 = g_csr[i + 2], s3 = g_csr[i + 3];
        float4 a0 = y4[s0 * 32 + lane];
        float4 a1 = y4[s1 * 32 + lane];
        float4 a2 = y4[s2 * 32 + lane];
        float4 a3 = y4[s3 * 32 + lane];
        acc.x += (a0.x + a1.x) + (a2.x + a3.x);
        acc.y += (a0.y + a1.y) + (a2.y + a3.y);
        acc.z += (a0.z + a1.z) + (a2.z + a3.z);
        acc.w += (a0.w + a1.w) + (a2.w + a3.w);
    }
    for (; i < end; i++) {
        int s = g_csr[i];
        float4 a = y4[s * 32 + lane];
        acc.x += a.x; acc.y += a.y; acc.z += a.z; acc.w += a.w;
    }

    float d = g_dinv[warp];
    float4 bv = ((const float4*)bias)[lane];
    float4 r;
    r.x = fmaxf(fmaf(acc.x, d, bv.x), 0.0f);
    r.y = fmaxf(fmaf(acc.y, d, bv.y), 0.0f);
    r.z = fmaxf(fmaf(acc.z, d, bv.z), 0.0f);
    r.w = fmaxf(fmaf(acc.w, d, bv.w), 0.0f);
    ((float4*)out)[warp * 32 + lane] = r;

    if (POOL) {
        int g = batch[warp];
        float* p = &g_pool[g * FD + lane * 4];
        atomicAdd(p + 0, r.x);
        atomicAdd(p + 1, r.y);
        atomicAdd(p + 2, r.z);
        atomicAdd(p + 3, r.w);
    }
}

// ---------------- head: logits = (pool/cnt) @ lin_w + lin_b ------------------
__global__ void head_kernel(const float* __restrict__ lin_w,
                            const float* __restrict__ lin_b,
                            float* __restrict__ out)
{
    int g = blockIdx.x;     // 64 blocks, 128 threads
    int t = threadIdx.x;
    if (g == 0 && t == 0) g_barrier = 0;   // reset software grid barrier
    float invc = 1.0f / fmaxf((float)g_gcnt[g], 1.0f);
    float v = g_pool[g * FD + t] * invc;
    __shared__ float red[FD];
    for (int c = 0; c < NC; c++) {
        red[t] = v * lin_w[t * NC + c];
        __syncthreads();
        for (int off = 64; off > 0; off >>= 1) {
            if (t < off) red[t] += red[t + off];
            __syncthreads();
        }
        if (t == 0) out[g * NC + c] = red[0] + lin_b[c];
        __syncthreads();
    }
}

// ---------------- launch -----------------------------------------------------
extern "C" void kernel_launch(void* const* d_in, const int* in_sizes, int n_in,
                              void* d_out, int out_size)
{
    const float* x     = (const float*)d_in[0];
    const int*   ei    = (const int*)  d_in[1];
    const int*   batch = (const int*)  d_in[2];
    const float* W1    = (const float*)d_in[3];
    const float* b1    = (const float*)d_in[4];
    const float* W2    = (const float*)d_in[5];
    const float* b2    = (const float*)d_in[6];
    const float* lw    = (const float*)d_in[7];
    const float* lb    = (const float*)d_in[8];
    float* out = (float*)d_out;

    const int* src = ei;        // edge_index[0]
    const int* dst = ei + NE;   // edge_index[1]

    float* y = nullptr; float* h = nullptr;
    cudaGetSymbolAddress((void**)&y, g_y);
    cudaGetSymbolAddress((void**)&h, g_h);

    cudaFuncSetAttribute(gemm_scale_kernel,
                         cudaFuncAttributeMaxDynamicSharedMemorySize, GEMM_SMEM);

    const int edgeBlocks = (NE + 255) / 256;       // 2500
    const int gemmBlocks = (NN + 127) / 128;       // 313
    const int aggBlocks  = (NN * 32 + 255) / 256;  // 5000

    // ncu (-s 5 -c 1) lands on MY 4th launch -> agg1 this round.
    prep_kernel<<<NB, 1024>>>(src, dst, batch);                      // 1
    fill_kernel<<<edgeBlocks, 256>>>(src, dst);                      // 2
    gemm_scale_kernel<<<gemmBlocks, 256, GEMM_SMEM>>>(x, W1, y, NN); // 3
    agg_kernel<false><<<aggBlocks, 256>>>(y, b1, batch, h);          // 4 <-- profiled

    gemm_scale_kernel<<<gemmBlocks, 256, GEMM_SMEM>>>(h, W2, y, NN); // 5
    agg_kernel<true><<<aggBlocks, 256>>>(y, b2, batch, h);           // 6

    head_kernel<<<NG, FD>>>(lw, lb, out);                            // 7
}

// round 8
// speedup vs baseline: 1.9592x; 1.4763x over previous
#include <cuda_runtime.h>
#include <cuda_bf16.h>

#define NN 40000      // nodes
#define NE 640000     // edges
#define FD 128        // feature / hidden dim
#define NG 64         // graphs
#define NC 10         // classes
#define SCAN_BLKS 40  // 40 * 1024 = 40960 >= NN
#define NB 128        // persistent prep blocks (co-resident on 148 SMs)

// ---------------- scratch (device globals; no allocations allowed) ----------
__device__ int   g_deg[NN];
__device__ int   g_rowptr[NN + 1];
__device__ int   g_cursor[NN];
__device__ int   g_csr[NE];
__device__ float g_dinv[NN];
__device__ int   g_gcnt[NG];
__device__ int   g_gstart[NG];
__device__ int   g_bsum[SCAN_BLKS];
__device__ float g_y[NN * FD];
__device__ float g_h[NN * FD];
__device__ unsigned g_barrier;     // software grid barrier (reset by gstart_kernel)

// ---------------- fused prep: zero + deg + node + scan (persistent) ---------
__device__ __forceinline__ void gsync(unsigned target) {
    __syncthreads();
    __threadfence();
    if (threadIdx.x == 0) {
        atomicAdd(&g_barrier, 1u);
        volatile unsigned* p = &g_barrier;          // cheap load-poll, no RMW storm
        while (*p < target) { }
    }
    __syncthreads();
    __threadfence();
}

__global__ __launch_bounds__(1024) void prep_kernel(
    const int* __restrict__ dst, const int* __restrict__ batch)
{
    int b = blockIdx.x, t = threadIdx.x;
    int gt = b * 1024 + t;                 // 0 .. 131071
    const int GSTRIDE = NB * 1024;

    // phase 0: zero scratch
    for (int i = gt; i < NN; i += GSTRIDE) g_deg[i] = 0;
    if (gt < NG) g_gcnt[gt] = 0;
    gsync(NB);

    // phase 1: in-degree count (REDG, no return)
    for (int e = gt; e < NE; e += GSTRIDE) atomicAdd(&g_deg[dst[e]], 1);
    gsync(2u * NB);

    // phase 2: dinv + graph counts + block-local exclusive scan (blocks 0..39)
    if (gt < NN) {
        g_dinv[gt] = rsqrtf((float)(g_deg[gt] + 1));
        atomicAdd(&g_gcnt[batch[gt]], 1);
    }
    __shared__ int wsum[32];
    int localExcl = 0;
    if (b < SCAN_BLKS) {
        int v = (gt < NN) ? g_deg[gt] : 0;
        int lane = t & 31, w = t >> 5;
        int x = v;
#pragma unroll
        for (int o = 1; o < 32; o <<= 1) {
            int y = __shfl_up_sync(0xffffffffu, x, o);
            if (lane >= o) x += y;
        }
        if (lane == 31) wsum[w] = x;
        __syncthreads();
        if (w == 0) {
            int s = wsum[lane];
#pragma unroll
            for (int o = 1; o < 32; o <<= 1) {
                int y = __shfl_up_sync(0xffffffffu, s, o);
                if (lane >= o) s += y;
            }
            wsum[lane] = s;
        }
        __syncthreads();
        int incl = x + ((w > 0) ? wsum[w - 1] : 0);
        localExcl = incl - v;
        if (t == 1023) g_bsum[b] = incl;
    }
    gsync(3u * NB);

    // phase 3: apply block offsets + cursor init (parallel bsum fetch -> smem)
    if (b < SCAN_BLKS) {
        __shared__ int sb[SCAN_BLKS];
        __shared__ int soff;
        if (t < SCAN_BLKS) sb[t] = g_bsum[t];
        __syncthreads();
        if (t == 0) {
            int s = 0;
            for (int j = 0; j < b; j++) s += sb[j];
            soff = s;
        }
        __syncthreads();
        if (gt < NN) {
            int r = localExcl + soff;
            g_rowptr[gt] = r;
            g_cursor[gt] = r;
        }
    }
    if (gt == 0) g_rowptr[NN] = NE;
}

// ---------------- graph start offsets (exclusive scan of gcnt) + bar reset --
__global__ void gstart_kernel() {
    int t = threadIdx.x;                   // 64 threads
    if (t == 0) g_barrier = 0;             // reset grid barrier for next replay
    int v = g_gcnt[t];
    int x = v;
#pragma unroll
    for (int o = 1; o < 32; o <<= 1) {
        int y = __shfl_up_sync(0xffffffffu, x, o);
        if ((t & 31) >= o) x += y;
    }
    __shared__ int incl[64];
    incl[t] = x;
    __syncthreads();
    int inc = x + ((t >= 32) ? incl[31] : 0);
    g_gstart[t] = inc - v;                 // exclusive prefix
}

// ---------------- CSR fill ---------------------------------------------------
__global__ void fill_kernel(const int* __restrict__ src, const int* __restrict__ dst) {
    int e = blockIdx.x * blockDim.x + threadIdx.x;
    if (e < NE) {
        int d = dst[e];
        int pos = atomicAdd(&g_cursor[d], 1);
        g_csr[pos] = src[e];
    }
}

// ---------------- GEMM: Y = (A @ W) * dinv[row] ------------------------------
// 256 threads, tile 128x128, 8x8 micro-tile split 4+4 (conflict-free LDS),
// double-buffered dynamic smem, one barrier per K-chunk.
#define WS_OFF(s)  ((s) * 4096)
#define AS_OFF(s)  (8192 + (s) * 4224)

__global__ __launch_bounds__(256) void gemm_scale_kernel(
    const float* __restrict__ A, const float* __restrict__ W,
    float* __restrict__ Y, int nrows)
{
    extern __shared__ float sm[];

    int tid  = threadIdx.x;
    int row0 = blockIdx.x * 128;
    int tx = tid & 15, ty = tid >> 4;

    float acc[8][8];
#pragma unroll
    for (int r = 0; r < 8; r++)
#pragma unroll
        for (int c = 0; c < 8; c++) acc[r][c] = 0.0f;

    const float4* A4 = (const float4*)A;
    const float4* W4 = (const float4*)W;

    auto load_stage = [&](int s, int k0) {
        float4* Wsm4 = (float4*)&sm[WS_OFF(s)];
#pragma unroll
        for (int j = tid; j < 1024; j += 256)
            Wsm4[j] = W4[k0 * 32 + j];
#pragma unroll
        for (int j = tid; j < 1024; j += 256) {
            int r = j >> 3, kq = j & 7;
            int gr = row0 + r;
            float4 v = (gr < nrows) ? A4[gr * 32 + (k0 >> 2) + kq]
                                    : make_float4(0.f, 0.f, 0.f, 0.f);
            int kk = kq * 4;
            float* As = &sm[AS_OFF(s)];
            As[(kk + 0) * 132 + r] = v.x;
            As[(kk + 1) * 132 + r] = v.y;
            As[(kk + 2) * 132 + r] = v.z;
            As[(kk + 3) * 132 + r] = v.w;
        }
    };

    load_stage(0, 0);
    __syncthreads();

#pragma unroll
    for (int chunk = 0; chunk < 4; chunk++) {
        int s = chunk & 1;
        if (chunk < 3) load_stage(s ^ 1, (chunk + 1) * 32);

        const float* Ws = &sm[WS_OFF(s)];
        const float* As = &sm[AS_OFF(s)];
#pragma unroll 8
        for (int k = 0; k < 32; k++) {
            float4 a0 = *(const float4*)&As[k * 132 + ty * 4];
            float4 a1 = *(const float4*)&As[k * 132 + 64 + ty * 4];
            float4 w0 = *(const float4*)&Ws[k * 128 + tx * 4];
            float4 w1 = *(const float4*)&Ws[k * 128 + 64 + tx * 4];
            float a[8] = {a0.x, a0.y, a0.z, a0.w, a1.x, a1.y, a1.z, a1.w};
            float w[8] = {w0.x, w0.y, w0.z, w0.w, w1.x, w1.y, w1.z, w1.w};
#pragma unroll
            for (int r = 0; r < 8; r++)
#pragma unroll
                for (int c = 0; c < 8; c++)
                    acc[r][c] = fmaf(a[r], w[c], acc[r][c]);
        }
        __syncthreads();
    }

#pragma unroll
    for (int rr = 0; rr < 8; rr++) {
        int lr = (rr < 4) ? (ty * 4 + rr) : (64 + ty * 4 + rr - 4);
        int gr = row0 + lr;
        if (gr < nrows) {
            float d = g_dinv[gr];
            float4 o0 = make_float4(acc[rr][0] * d, acc[rr][1] * d, acc[rr][2] * d, acc[rr][3] * d);
            float4 o1 = make_float4(acc[rr][4] * d, acc[rr][5] * d, acc[rr][6] * d, acc[rr][7] * d);
            *(float4*)&Y[gr * FD + tx * 4]      = o0;
            *(float4*)&Y[gr * FD + 64 + tx * 4] = o1;
        }
    }
}
#define GEMM_SMEM 66560

// ---------------- aggregation: out[v] = relu(dinv[v]*(y[v]+sum y[src]) + b) --
__global__ __launch_bounds__(256) void agg_kernel(
    const float* __restrict__ y, const float* __restrict__ bias,
    float* __restrict__ out)
{
    int warp = (blockIdx.x * blockDim.x + threadIdx.x) >> 5;
    int lane = threadIdx.x & 31;
    if (warp >= NN) return;

    const float4* y4 = (const float4*)y;
    float4 acc = y4[warp * 32 + lane];        // self-loop term (y already dinv-scaled)

    int i   = g_rowptr[warp];
    int end = g_rowptr[warp + 1];

    for (; i + 16 <= end; i += 16) {
        int idx[16];
#pragma unroll
        for (int j = 0; j < 16; j++) idx[j] = g_csr[i + j];
        float4 v[16];
#pragma unroll
        for (int j = 0; j < 16; j++) v[j] = y4[idx[j] * 32 + lane];
        float sx = 0.f, sy = 0.f, sz = 0.f, sw = 0.f;
#pragma unroll
        for (int j = 0; j < 16; j++) { sx += v[j].x; sy += v[j].y; sz += v[j].z; sw += v[j].w; }
        acc.x += sx; acc.y += sy; acc.z += sz; acc.w += sw;
    }
    for (; i + 4 <= end; i += 4) {
        int s0 = g_csr[i], s1 = g_csr[i + 1], s2 = g_csr[i + 2], s3 = g_csr[i + 3];
        float4 a0 = y4[s0 * 32 + lane];
        float4 a1 = y4[s1 * 32 + lane];
        float4 a2 = y4[s2 * 32 + lane];
        float4 a3 = y4[s3 * 32 + lane];
        acc.x += (a0.x + a1.x) + (a2.x + a3.x);
        acc.y += (a0.y + a1.y) + (a2.y + a3.y);
        acc.z += (a0.z + a1.z) + (a2.z + a3.z);
        acc.w += (a0.w + a1.w) + (a2.w + a3.w);
    }
    for (; i < end; i++) {
        int s = g_csr[i];
        float4 a = y4[s * 32 + lane];
        acc.x += a.x; acc.y += a.y; acc.z += a.z; acc.w += a.w;
    }

    float d = g_dinv[warp];
    float4 bv = ((const float4*)bias)[lane];
    float4 r;
    r.x = fmaxf(fmaf(acc.x, d, bv.x), 0.0f);
    r.y = fmaxf(fmaf(acc.y, d, bv.y), 0.0f);
    r.z = fmaxf(fmaf(acc.z, d, bv.z), 0.0f);
    r.w = fmaxf(fmaf(acc.w, d, bv.w), 0.0f);
    ((float4*)out)[warp * 32 + lane] = r;
}

// ---------------- fused pool + head: no atomics (batch is sorted) ------------
// 64 blocks x 512 threads: 4 row-stripes of 128 cols sum h over the graph's
// contiguous node range; then 10 warps compute the 10 logits.
__global__ __launch_bounds__(512) void pool_head_kernel(
    const float* __restrict__ lin_w, const float* __restrict__ lin_b,
    float* __restrict__ out)
{
    int g = blockIdx.x;
    int t = threadIdx.x;
    int col = t & 127, stripe = t >> 7;    // stripe 0..3

    int start = g_gstart[g];
    int cnt   = g_gcnt[g];

    float acc = 0.0f;
    for (int r = start + stripe; r < start + cnt; r += 4)
        acc += g_h[r * FD + col];

    __shared__ float red[512];
    __shared__ float pooled[FD];
    red[t] = acc;
    __syncthreads();
    if (stripe == 0)
        pooled[col] = (red[col] + red[col + 128] + red[col + 256] + red[col + 384])
                      / fmaxf((float)cnt, 1.0f);
    __syncthreads();

    int wid = t >> 5, lane = t & 31;
    if (wid < NC) {
        float s = 0.0f;
#pragma unroll
        for (int k = 0; k < 4; k++) {
            int f = lane + 32 * k;
            s += pooled[f] * lin_w[f * NC + wid];
        }
#pragma unroll
        for (int o = 16; o > 0; o >>= 1)
            s += __shfl_down_sync(0xffffffffu, s, o);
        if (lane == 0) out[g * NC + wid] = s + lin_b[wid];
    }
}

// ---------------- launch -----------------------------------------------------
extern "C" void kernel_launch(void* const* d_in, const int* in_sizes, int n_in,
                              void* d_out, int out_size)
{
    const float* x     = (const float*)d_in[0];
    const int*   ei    = (const int*)  d_in[1];
    const int*   batch = (const int*)  d_in[2];
    const float* W1    = (const float*)d_in[3];
    const float* b1    = (const float*)d_in[4];
    const float* W2    = (const float*)d_in[5];
    const float* b2    = (const float*)d_in[6];
    const float* lw    = (const float*)d_in[7];
    const float* lb    = (const float*)d_in[8];
    float* out = (float*)d_out;

    const int* src = ei;        // edge_index[0]
    const int* dst = ei + NE;   // edge_index[1]

    float* y = nullptr; float* h = nullptr;
    cudaGetSymbolAddress((void**)&y, g_y);
    cudaGetSymbolAddress((void**)&h, g_h);

    cudaFuncSetAttribute(gemm_scale_kernel,
                         cudaFuncAttributeMaxDynamicSharedMemorySize, GEMM_SMEM);

    const int edgeBlocks = (NE + 255) / 256;       // 2500
    const int gemmBlocks = (NN + 127) / 128;       // 313
    const int aggBlocks  = (NN * 32 + 255) / 256;  // 5000

    // ncu (-s 5 -c 1) lands on MY 4th launch -> fill_kernel this round.
    prep_kernel<<<NB, 1024>>>(dst, batch);                            // 1
    gemm_scale_kernel<<<gemmBlocks, 256, GEMM_SMEM>>>(x, W1, y, NN);  // 2
    gstart_kernel<<<1, 64>>>();                                       // 3
    fill_kernel<<<edgeBlocks, 256>>>(src, dst);                       // 4 <-- profiled

    agg_kernel<<<aggBlocks, 256>>>(y, b1, h);                         // 5

    gemm_scale_kernel<<<gemmBlocks, 256, GEMM_SMEM>>>(h, W2, y, NN);  // 6
    agg_kernel<<<aggBlocks, 256>>>(y, b2, h);                         // 7

    pool_head_kernel<<<NG, 512>>>(lw, lb, out);                       // 8
}